// round 1
// baseline (speedup 1.0000x reference)
#include <cuda_runtime.h>
#include <cstdint>

// Problem constants (fixed by the dataset)
#define NMAX    50000
#define INDIM   100
#define D1      512
#define D2      256
#define D3      128
#define D4      200

// Scratch (device globals; no allocation allowed)
__device__ float g_deg[NMAX];
__device__ float g_dinv[NMAX];
__device__ int   g_group[NMAX];
__device__ float g_gcnt[4];
__device__ float g_gsum[4 * D4];
__device__ float g_bufA[(size_t)NMAX * 256];  // Hs scratch (max scatter dim 256)
__device__ float g_bufB[(size_t)NMAX * 256];  // Acc scratch
__device__ float g_bufC[(size_t)NMAX * 512];  // layer outputs (max 512)

// ---------------------------------------------------------------------------
// init: deg=1 (self loop), zero gsum/gcnt
__global__ void init_kernel(int M) {
    int i = blockIdx.x * blockDim.x + threadIdx.x;
    if (i < M) g_deg[i] = 1.0f;
    if (i < 4 * D4) g_gsum[i] = 0.0f;
    if (i < 4) g_gcnt[i] = 0.0f;
}

// deg[dst] += 1 per edge
__global__ void deg_kernel(const int* __restrict__ ei, int E) {
    int e = blockIdx.x * blockDim.x + threadIdx.x;
    if (e >= E) return;
    atomicAdd(&g_deg[ei[E + e]], 1.0f);
}

// dinv = rsqrt(deg); group id per node; group counts
__global__ void node_prep(const float* __restrict__ x, const float* __restrict__ nf, int M) {
    int i = blockIdx.x * blockDim.x + threadIdx.x;
    if (i >= M) return;
    g_dinv[i] = rsqrtf(g_deg[i]);
    const float* row = x + (size_t)i * INDIM;
    bool e0 = true, e1 = true, e2 = true;
    #pragma unroll 4
    for (int j = 0; j < INDIM; j++) {
        float a = row[j];
        e0 = e0 && (a == __ldg(&nf[j]));
        e1 = e1 && (a == __ldg(&nf[INDIM + j]));
        e2 = e2 && (a == __ldg(&nf[2 * INDIM + j]));
    }
    int g = e0 ? 0 : (e1 ? 3 : (e2 ? 1 : 2));
    g_group[i] = g;
    atomicAdd(&g_gcnt[g], 1.0f);
}

// h = src*dinv[row]; write to A (Hs) and B (Acc init = self loop)
__global__ void scale_dual(const float* __restrict__ src, float* __restrict__ A,
                           float* __restrict__ B, int M, int dim) {
    size_t idx = (size_t)blockIdx.x * blockDim.x + threadIdx.x;
    size_t total = (size_t)M * dim;
    if (idx >= total) return;
    int r = (int)(idx / dim);
    float v = src[idx] * g_dinv[r];
    A[idx] = v;
    B[idx] = v;
}

// Acc[dst] += Hs[src] over edges, vectorized float4 channels
__global__ void scatter_add(const float* __restrict__ Hs, float* __restrict__ Acc,
                            const int* __restrict__ ei, int E, int dim) {
    int dim4 = dim >> 2;
    size_t idx = (size_t)blockIdx.x * blockDim.x + threadIdx.x;
    size_t total = (size_t)E * dim4;
    if (idx >= total) return;
    int e = (int)(idx / dim4);
    int c = (int)(idx - (size_t)e * dim4);
    int s = ei[e];
    int d = ei[E + e];
    float4 v = ((const float4*)(Hs + (size_t)s * dim))[c];
    float* dst = Acc + (size_t)d * dim + c * 4;
    atomicAdd(dst + 0, v.x);
    atomicAdd(dst + 1, v.y);
    atomicAdd(dst + 2, v.z);
    atomicAdd(dst + 3, v.w);
}

// out = relu(dinv[i]*Acc + b)   (post-aggregation epilogue)
__global__ void finalize_plain(const float* __restrict__ Acc, const float* __restrict__ bias,
                               float* __restrict__ out, int M, int dim) {
    size_t idx = (size_t)blockIdx.x * blockDim.x + threadIdx.x;
    size_t total = (size_t)M * dim;
    if (idx >= total) return;
    int r = (int)(idx / dim);
    int c = (int)(idx - (size_t)r * dim);
    float v = fmaxf(g_dinv[r] * Acc[idx] + bias[c], 0.0f);
    out[idx] = v;
}

// fused layer3-finalize + layer4 pre-scale:  h = relu(dinv*Acc+b)*dinv -> Hs, Acc2
__global__ void finalize_hs(const float* __restrict__ Acc, const float* __restrict__ bias,
                            float* __restrict__ Hs, float* __restrict__ Acc2, int M, int dim) {
    size_t idx = (size_t)blockIdx.x * blockDim.x + threadIdx.x;
    size_t total = (size_t)M * dim;
    if (idx >= total) return;
    int r = (int)(idx / dim);
    int c = (int)(idx - (size_t)r * dim);
    float di = g_dinv[r];
    float v = fmaxf(di * Acc[idx] + bias[c], 0.0f) * di;
    Hs[idx] = v;
    Acc2[idx] = v;
}

// ---------------------------------------------------------------------------
// SGEMM: C[M,N] from A[M,K] @ W[K,N].
// scaleA: multiply A rows by dinv[row] at load.
// epi=0: C = relu(acc + bias)
// epi=1: v = dinv[row]*acc;  C = v; C2 = v   (dual-write for scatter stage)
__global__ __launch_bounds__(256) void gemm_kernel(
    const float* __restrict__ A, const float* __restrict__ W,
    const float* __restrict__ bias,
    float* __restrict__ C, float* __restrict__ C2,
    int M, int K, int N, int scaleA, int epi)
{
    __shared__ float As[16][64];
    __shared__ float Bs[16][64];

    int tid = threadIdx.x;
    int r0 = blockIdx.x * 64;
    int n0 = blockIdx.y * 64;
    int tx = tid & 15, ty = tid >> 4;

    // A tile loader: row la_r (0..63), k offset la_k (0,4,8,12)
    int la_r = tid >> 2;
    int la_k = (tid & 3) * 4;
    int arow = r0 + la_r;
    bool arow_ok = arow < M;
    float dscale = 1.0f;
    if (scaleA && arow_ok) dscale = g_dinv[arow];

    // B tile loader: k row lb_k (0..15), col offset lb_n
    int lb_k = tid >> 4;
    int lb_n = (tid & 15) * 4;

    float acc[4][4];
    #pragma unroll
    for (int i = 0; i < 4; i++)
        #pragma unroll
        for (int j = 0; j < 4; j++) acc[i][j] = 0.0f;

    for (int kt = 0; kt < K; kt += 16) {
        // load A
        float4 a = make_float4(0.f, 0.f, 0.f, 0.f);
        int kg = kt + la_k;
        if (arow_ok) {
            if (kg + 3 < K) {
                a = *(const float4*)(A + (size_t)arow * K + kg);
            } else {
                const float* ap = A + (size_t)arow * K;
                if (kg + 0 < K) a.x = ap[kg + 0];
                if (kg + 1 < K) a.y = ap[kg + 1];
                if (kg + 2 < K) a.z = ap[kg + 2];
                if (kg + 3 < K) a.w = ap[kg + 3];
            }
        }
        a.x *= dscale; a.y *= dscale; a.z *= dscale; a.w *= dscale;
        As[la_k + 0][la_r] = a.x;
        As[la_k + 1][la_r] = a.y;
        As[la_k + 2][la_r] = a.z;
        As[la_k + 3][la_r] = a.w;

        // load B
        float4 b = make_float4(0.f, 0.f, 0.f, 0.f);
        int kb = kt + lb_k;
        int nb = n0 + lb_n;
        if (kb < K) {
            if (nb + 3 < N) {
                b = *(const float4*)(W + (size_t)kb * N + nb);
            } else {
                const float* wp = W + (size_t)kb * N;
                if (nb + 0 < N) b.x = wp[nb + 0];
                if (nb + 1 < N) b.y = wp[nb + 1];
                if (nb + 2 < N) b.z = wp[nb + 2];
                if (nb + 3 < N) b.w = wp[nb + 3];
            }
        }
        *(float4*)&Bs[lb_k][lb_n] = b;

        __syncthreads();

        #pragma unroll
        for (int k = 0; k < 16; k++) {
            float4 av = *(const float4*)&As[k][ty * 4];
            float4 bv = *(const float4*)&Bs[k][tx * 4];
            acc[0][0] += av.x * bv.x; acc[0][1] += av.x * bv.y;
            acc[0][2] += av.x * bv.z; acc[0][3] += av.x * bv.w;
            acc[1][0] += av.y * bv.x; acc[1][1] += av.y * bv.y;
            acc[1][2] += av.y * bv.z; acc[1][3] += av.y * bv.w;
            acc[2][0] += av.z * bv.x; acc[2][1] += av.z * bv.y;
            acc[2][2] += av.z * bv.z; acc[2][3] += av.z * bv.w;
            acc[3][0] += av.w * bv.x; acc[3][1] += av.w * bv.y;
            acc[3][2] += av.w * bv.z; acc[3][3] += av.w * bv.w;
        }
        __syncthreads();
    }

    // epilogue
    #pragma unroll
    for (int i = 0; i < 4; i++) {
        int r = r0 + ty * 4 + i;
        if (r >= M) continue;
        float di = (epi == 1) ? g_dinv[r] : 0.0f;
        #pragma unroll
        for (int j = 0; j < 4; j++) {
            int n = n0 + tx * 4 + j;
            if (n >= N) continue;
            size_t off = (size_t)r * N + n;
            if (epi == 0) {
                C[off] = fmaxf(acc[i][j] + bias[n], 0.0f);
            } else {
                float v = di * acc[i][j];
                C[off] = v;
                C2[off] = v;
            }
        }
    }
}

// ---------------------------------------------------------------------------
// grouped sum of out4 rows into gsum[4][200] via smem partials
__global__ void group_reduce(const float* __restrict__ out4, int M) {
    __shared__ float s[4 * D4];
    for (int i = threadIdx.x; i < 4 * D4; i += blockDim.x) s[i] = 0.0f;
    __syncthreads();
    int base = blockIdx.x * 256;
    for (int n = 0; n < 256; n++) {
        int node = base + n;
        if (node >= M) break;
        int g = g_group[node];
        const float* row = out4 + (size_t)node * D4;
        // each thread owns fixed columns -> no races across nodes
        for (int c = threadIdx.x; c < D4; c += blockDim.x)
            s[g * D4 + c] += row[c];
    }
    __syncthreads();
    for (int i = threadIdx.x; i < 4 * D4; i += blockDim.x)
        if (s[i] != 0.0f) atomicAdd(&g_gsum[i], s[i]);
}

__global__ void final_out(float* __restrict__ out) {
    int i = blockIdx.x * blockDim.x + threadIdx.x;
    if (i >= 4 * D4) return;
    float c = g_gcnt[i / D4];
    out[i] = (c > 0.0f) ? g_gsum[i] / c : 0.0f;
}

// ---------------------------------------------------------------------------
static inline int ceil_div(long long a, long long b) { return (int)((a + b - 1) / b); }

extern "C" void kernel_launch(void* const* d_in, const int* in_sizes, int n_in,
                              void* d_out, int out_size) {
    const float* x  = (const float*)d_in[0];
    const float* nf = (const float*)d_in[1];
    const int*   ei = (const int*)d_in[2];
    const float* W1 = (const float*)d_in[3];
    const float* b1 = (const float*)d_in[4];
    const float* W2 = (const float*)d_in[5];
    const float* b2 = (const float*)d_in[6];
    const float* W3 = (const float*)d_in[7];
    const float* b3 = (const float*)d_in[8];
    const float* W4 = (const float*)d_in[9];
    const float* b4 = (const float*)d_in[10];
    float* out = (float*)d_out;

    int M = in_sizes[0] / INDIM;     // 50000
    int E = in_sizes[2] / 2;         // 800000

    float *bufA, *bufB, *bufC;
    cudaGetSymbolAddress((void**)&bufA, g_bufA);
    cudaGetSymbolAddress((void**)&bufB, g_bufB);
    cudaGetSymbolAddress((void**)&bufC, g_bufC);

    const int T = 256;

    // degrees, groups
    init_kernel<<<ceil_div(M, T), T>>>(M);
    deg_kernel<<<ceil_div(E, T), T>>>(ei, E);
    node_prep<<<ceil_div(M, T), T>>>(x, nf, M);

    // ---- Layer 1: aggregate-first (dim 100), then GEMM K=100 -> 512
    scale_dual<<<ceil_div((long long)M * INDIM, T), T>>>(x, bufA, bufB, M, INDIM);
    scatter_add<<<ceil_div((long long)E * (INDIM / 4), T), T>>>(bufA, bufB, ei, E, INDIM);
    {
        dim3 g(ceil_div(M, 64), ceil_div(D1, 64));
        gemm_kernel<<<g, 256>>>(bufB, W1, b1, bufC, nullptr, M, INDIM, D1, 1, 0);
    }

    // ---- Layer 2: GEMM K=512 -> 256 (dual write Hs/Acc), aggregate, finalize
    {
        dim3 g(ceil_div(M, 64), ceil_div(D2, 64));
        gemm_kernel<<<g, 256>>>(bufC, W2, nullptr, bufA, bufB, M, D1, D2, 0, 1);
    }
    scatter_add<<<ceil_div((long long)E * (D2 / 4), T), T>>>(bufA, bufB, ei, E, D2);
    finalize_plain<<<ceil_div((long long)M * D2, T), T>>>(bufB, b2, bufC, M, D2);

    // ---- Layer 3: GEMM K=256 -> 128, aggregate, finalize fused with L4 pre-scale
    {
        dim3 g(ceil_div(M, 64), ceil_div(D3, 64));
        gemm_kernel<<<g, 256>>>(bufC, W3, nullptr, bufA, bufB, M, D2, D3, 0, 1);
    }
    scatter_add<<<ceil_div((long long)E * (D3 / 4), T), T>>>(bufA, bufB, ei, E, D3);
    finalize_hs<<<ceil_div((long long)M * D3, T), T>>>(bufB, b3, bufA, bufB, M, D3);

    // ---- Layer 4: aggregate-first (dim 128), GEMM K=128 -> 200 with bias+relu
    scatter_add<<<ceil_div((long long)E * (D3 / 4), T), T>>>(bufA, bufB, ei, E, D3);
    {
        dim3 g(ceil_div(M, 64), ceil_div(D4, 64));
        gemm_kernel<<<g, 256>>>(bufB, W4, b4, bufC, nullptr, M, D3, D4, 1, 0);
    }

    // ---- grouped mean pooling
    group_reduce<<<ceil_div(M, 256), 128>>>(bufC, M);
    final_out<<<ceil_div(4 * D4, T), T>>>(out);
}

// round 2
// speedup vs baseline: 1.8853x; 1.8853x over previous
#include <cuda_runtime.h>
#include <cstdint>

#define NMAX    50000
#define EMAX    800000
#define INDIM   100
#define D1      512
#define D2      256
#define D3      128
#define D4      200

// Scratch
__device__ float g_dinv[NMAX];
__device__ int   g_group[NMAX];
__device__ float g_gcnt[4];
__device__ float g_gsum[4 * D4];
__device__ int   g_cnt[NMAX];
__device__ int   g_fill[NMAX];
__device__ int   g_rowptr[NMAX + 1];
__device__ int   g_csr[EMAX];
__device__ float g_bufA[(size_t)NMAX * 256];
__device__ float g_bufB[(size_t)NMAX * 256];
__device__ float g_bufC[(size_t)NMAX * 512];

// ---------------------------------------------------------------------------
__global__ void zero_kernel(int M) {
    int i = blockIdx.x * blockDim.x + threadIdx.x;
    if (i < M) { g_cnt[i] = 0; g_fill[i] = 0; }
    if (i < 4 * D4) g_gsum[i] = 0.0f;
    if (i < 4) g_gcnt[i] = 0.0f;
}

__global__ void count_kernel(const int* __restrict__ ei, int E) {
    int e = blockIdx.x * blockDim.x + threadIdx.x;
    if (e >= E) return;
    atomicAdd(&g_cnt[ei[E + e]], 1);
}

// single-block chunked Hillis-Steele scan -> exclusive rowptr
__global__ void scan_kernel(int M) {
    __shared__ int buf[2][1024];
    __shared__ int carry;
    int t = threadIdx.x;
    if (t == 0) { carry = 0; g_rowptr[0] = 0; }
    __syncthreads();
    for (int base = 0; base < M; base += 1024) {
        int i = base + t;
        int v = (i < M) ? g_cnt[i] : 0;
        int sel = 0;
        buf[0][t] = v;
        __syncthreads();
        #pragma unroll
        for (int off = 1; off < 1024; off <<= 1) {
            int x = buf[sel][t];
            if (t >= off) x += buf[sel][t - off];
            buf[sel ^ 1][t] = x;
            sel ^= 1;
            __syncthreads();
        }
        if (i < M) g_rowptr[i + 1] = carry + buf[sel][t];
        int total = buf[sel][1023];
        __syncthreads();
        if (t == 0) carry += total;
        __syncthreads();
    }
}

__global__ void fill_kernel(const int* __restrict__ ei, int E) {
    int e = blockIdx.x * blockDim.x + threadIdx.x;
    if (e >= E) return;
    int d = ei[E + e];
    int pos = atomicAdd(&g_fill[d], 1);
    g_csr[g_rowptr[d] + pos] = ei[e];
}

// dinv from rowptr (deg = in-deg + self loop); group id; group counts
__global__ void node_prep(const float* __restrict__ x, const float* __restrict__ nf, int M) {
    int i = blockIdx.x * blockDim.x + threadIdx.x;
    if (i >= M) return;
    float deg = (float)(g_rowptr[i + 1] - g_rowptr[i] + 1);
    g_dinv[i] = rsqrtf(deg);
    const float* row = x + (size_t)i * INDIM;
    bool e0 = true, e1 = true, e2 = true;
    #pragma unroll 4
    for (int j = 0; j < INDIM; j++) {
        float a = row[j];
        e0 = e0 && (a == __ldg(&nf[j]));
        e1 = e1 && (a == __ldg(&nf[INDIM + j]));
        e2 = e2 && (a == __ldg(&nf[2 * INDIM + j]));
    }
    int g = e0 ? 0 : (e1 ? 3 : (e2 ? 1 : 2));
    g_group[i] = g;
    atomicAdd(&g_gcnt[g], 1.0f);
}

// bufA = x * dinv[row]   (Hs for layer 1)
__global__ void scale_x(const float* __restrict__ x, float* __restrict__ out, int M) {
    size_t idx = (size_t)blockIdx.x * blockDim.x + threadIdx.x;
    size_t total = (size_t)M * INDIM;
    if (idx >= total) return;
    int r = (int)(idx / INDIM);
    out[idx] = x[idx] * g_dinv[r];
}

// ---------------------------------------------------------------------------
// Gather aggregation: one warp per dst node. acc = Hs[self] + sum Hs[neighbors]
// epi 0: out = dinv*acc
// epi 1: out = relu(dinv*acc + bias)
// epi 2: out = relu(dinv*acc + bias) * dinv
__global__ __launch_bounds__(256) void gather_kernel(
    const float* __restrict__ Hs, float* __restrict__ out,
    const float* __restrict__ bias, int M, int dim, int epi)
{
    int warp = (blockIdx.x * blockDim.x + threadIdx.x) >> 5;
    int lane = threadIdx.x & 31;
    if (warp >= M) return;
    int d4 = dim >> 2;
    int c0 = lane, c1 = lane + 32;
    bool p0 = c0 < d4, p1 = c1 < d4;
    int start = g_rowptr[warp], end = g_rowptr[warp + 1];
    float di = g_dinv[warp];

    float4 a0 = make_float4(0.f, 0.f, 0.f, 0.f);
    float4 a1 = make_float4(0.f, 0.f, 0.f, 0.f);
    const float* self = Hs + (size_t)warp * dim;
    if (p0) a0 = *(const float4*)(self + c0 * 4);
    if (p1) a1 = *(const float4*)(self + c1 * 4);

    int j = start;
    for (; j + 4 <= end; j += 4) {
        int s0 = g_csr[j], s1 = g_csr[j + 1], s2 = g_csr[j + 2], s3 = g_csr[j + 3];
        const float* r0 = Hs + (size_t)s0 * dim;
        const float* r1 = Hs + (size_t)s1 * dim;
        const float* r2 = Hs + (size_t)s2 * dim;
        const float* r3 = Hs + (size_t)s3 * dim;
        float4 v00, v10, v20, v30, v01, v11, v21, v31;
        if (p0) {
            v00 = *(const float4*)(r0 + c0 * 4);
            v10 = *(const float4*)(r1 + c0 * 4);
            v20 = *(const float4*)(r2 + c0 * 4);
            v30 = *(const float4*)(r3 + c0 * 4);
        }
        if (p1) {
            v01 = *(const float4*)(r0 + c1 * 4);
            v11 = *(const float4*)(r1 + c1 * 4);
            v21 = *(const float4*)(r2 + c1 * 4);
            v31 = *(const float4*)(r3 + c1 * 4);
        }
        if (p0) {
            a0.x += v00.x + v10.x + v20.x + v30.x;
            a0.y += v00.y + v10.y + v20.y + v30.y;
            a0.z += v00.z + v10.z + v20.z + v30.z;
            a0.w += v00.w + v10.w + v20.w + v30.w;
        }
        if (p1) {
            a1.x += v01.x + v11.x + v21.x + v31.x;
            a1.y += v01.y + v11.y + v21.y + v31.y;
            a1.z += v01.z + v11.z + v21.z + v31.z;
            a1.w += v01.w + v11.w + v21.w + v31.w;
        }
    }
    for (; j < end; j++) {
        int s = g_csr[j];
        const float* r = Hs + (size_t)s * dim;
        if (p0) {
            float4 v = *(const float4*)(r + c0 * 4);
            a0.x += v.x; a0.y += v.y; a0.z += v.z; a0.w += v.w;
        }
        if (p1) {
            float4 v = *(const float4*)(r + c1 * 4);
            a1.x += v.x; a1.y += v.y; a1.z += v.z; a1.w += v.w;
        }
    }

    float* orow = out + (size_t)warp * dim;
    if (p0) {
        float4 v;
        v.x = di * a0.x; v.y = di * a0.y; v.z = di * a0.z; v.w = di * a0.w;
        if (epi >= 1) {
            float4 b = *(const float4*)(bias + c0 * 4);
            v.x = fmaxf(v.x + b.x, 0.f); v.y = fmaxf(v.y + b.y, 0.f);
            v.z = fmaxf(v.z + b.z, 0.f); v.w = fmaxf(v.w + b.w, 0.f);
            if (epi == 2) { v.x *= di; v.y *= di; v.z *= di; v.w *= di; }
        }
        *(float4*)(orow + c0 * 4) = v;
    }
    if (p1) {
        float4 v;
        v.x = di * a1.x; v.y = di * a1.y; v.z = di * a1.z; v.w = di * a1.w;
        if (epi >= 1) {
            float4 b = *(const float4*)(bias + c1 * 4);
            v.x = fmaxf(v.x + b.x, 0.f); v.y = fmaxf(v.y + b.y, 0.f);
            v.z = fmaxf(v.z + b.z, 0.f); v.w = fmaxf(v.w + b.w, 0.f);
            if (epi == 2) { v.x *= di; v.y *= di; v.z *= di; v.w *= di; }
        }
        *(float4*)(orow + c1 * 4) = v;
    }
}

// ---------------------------------------------------------------------------
// SGEMM 128x64 tile, 8x4 micro-tile, 256 threads.
// epi 0: C = relu(acc + bias)
// epi 1: C = dinv[row] * acc
__global__ __launch_bounds__(256) void gemm_kernel(
    const float* __restrict__ A, const float* __restrict__ W,
    const float* __restrict__ bias, float* __restrict__ C,
    int M, int K, int N, int epi)
{
    __shared__ float As[16][132];
    __shared__ float Bs[16][64];

    int tid = threadIdx.x;
    int r0 = blockIdx.x * 128;
    int n0 = blockIdx.y * 64;
    int tx = tid & 15, ty = tid >> 4;

    int lar = tid >> 2;          // 0..63
    int lak = (tid & 3) << 2;    // 0,4,8,12
    int lbk = tid >> 4;          // 0..15
    int lbn = (tid & 15) << 2;   // 0..60

    float acc[8][4];
    #pragma unroll
    for (int i = 0; i < 8; i++)
        #pragma unroll
        for (int jj = 0; jj < 4; jj++) acc[i][jj] = 0.0f;

    for (int kt = 0; kt < K; kt += 16) {
        #pragma unroll
        for (int h = 0; h < 2; h++) {
            int r = r0 + lar + h * 64;
            int kg = kt + lak;
            float4 a = make_float4(0.f, 0.f, 0.f, 0.f);
            if (r < M) {
                if (kg + 3 < K) {
                    a = *(const float4*)(A + (size_t)r * K + kg);
                } else {
                    const float* ap = A + (size_t)r * K;
                    if (kg + 0 < K) a.x = ap[kg + 0];
                    if (kg + 1 < K) a.y = ap[kg + 1];
                    if (kg + 2 < K) a.z = ap[kg + 2];
                    if (kg + 3 < K) a.w = ap[kg + 3];
                }
            }
            As[lak + 0][lar + h * 64] = a.x;
            As[lak + 1][lar + h * 64] = a.y;
            As[lak + 2][lar + h * 64] = a.z;
            As[lak + 3][lar + h * 64] = a.w;
        }
        {
            int kb = kt + lbk;
            int nb = n0 + lbn;
            float4 b = make_float4(0.f, 0.f, 0.f, 0.f);
            if (kb < K) {
                if (nb + 3 < N) {
                    b = *(const float4*)(W + (size_t)kb * N + nb);
                } else {
                    const float* wp = W + (size_t)kb * N;
                    if (nb + 0 < N) b.x = wp[nb + 0];
                    if (nb + 1 < N) b.y = wp[nb + 1];
                    if (nb + 2 < N) b.z = wp[nb + 2];
                    if (nb + 3 < N) b.w = wp[nb + 3];
                }
            }
            *(float4*)&Bs[lbk][lbn] = b;
        }
        __syncthreads();

        #pragma unroll
        for (int k = 0; k < 16; k++) {
            float4 a0 = *(const float4*)&As[k][ty * 8];
            float4 a1 = *(const float4*)&As[k][ty * 8 + 4];
            float4 b  = *(const float4*)&Bs[k][tx * 4];
            float av[8] = {a0.x, a0.y, a0.z, a0.w, a1.x, a1.y, a1.z, a1.w};
            float bv[4] = {b.x, b.y, b.z, b.w};
            #pragma unroll
            for (int i = 0; i < 8; i++)
                #pragma unroll
                for (int jj = 0; jj < 4; jj++)
                    acc[i][jj] += av[i] * bv[jj];
        }
        __syncthreads();
    }

    #pragma unroll
    for (int i = 0; i < 8; i++) {
        int r = r0 + ty * 8 + i;
        if (r >= M) continue;
        float di = (epi == 1) ? g_dinv[r] : 0.0f;
        #pragma unroll
        for (int jj = 0; jj < 4; jj++) {
            int n = n0 + tx * 4 + jj;
            if (n >= N) continue;
            float v = acc[i][jj];
            if (epi == 0) v = fmaxf(v + bias[n], 0.0f);
            else          v = di * v;
            C[(size_t)r * N + n] = v;
        }
    }
}

// ---------------------------------------------------------------------------
__global__ void group_reduce(const float* __restrict__ out4, int M) {
    __shared__ float s[4 * D4];
    for (int i = threadIdx.x; i < 4 * D4; i += blockDim.x) s[i] = 0.0f;
    __syncthreads();
    int base = blockIdx.x * 256;
    for (int n = 0; n < 256; n++) {
        int node = base + n;
        if (node >= M) break;
        int g = g_group[node];
        const float* row = out4 + (size_t)node * D4;
        for (int c = threadIdx.x; c < D4; c += blockDim.x)
            s[g * D4 + c] += row[c];
    }
    __syncthreads();
    for (int i = threadIdx.x; i < 4 * D4; i += blockDim.x)
        if (s[i] != 0.0f) atomicAdd(&g_gsum[i], s[i]);
}

__global__ void final_out(float* __restrict__ out) {
    int i = blockIdx.x * blockDim.x + threadIdx.x;
    if (i >= 4 * D4) return;
    float c = g_gcnt[i / D4];
    out[i] = (c > 0.0f) ? g_gsum[i] / c : 0.0f;
}

// ---------------------------------------------------------------------------
static inline int ceil_div(long long a, long long b) { return (int)((a + b - 1) / b); }

extern "C" void kernel_launch(void* const* d_in, const int* in_sizes, int n_in,
                              void* d_out, int out_size) {
    const float* x  = (const float*)d_in[0];
    const float* nf = (const float*)d_in[1];
    const int*   ei = (const int*)d_in[2];
    const float* W1 = (const float*)d_in[3];
    const float* b1 = (const float*)d_in[4];
    const float* W2 = (const float*)d_in[5];
    const float* b2 = (const float*)d_in[6];
    const float* W3 = (const float*)d_in[7];
    const float* b3 = (const float*)d_in[8];
    const float* W4 = (const float*)d_in[9];
    const float* b4 = (const float*)d_in[10];
    float* out = (float*)d_out;

    int M = in_sizes[0] / INDIM;     // 50000
    int E = in_sizes[2] / 2;         // 800000

    float *bufA, *bufB, *bufC;
    cudaGetSymbolAddress((void**)&bufA, g_bufA);
    cudaGetSymbolAddress((void**)&bufB, g_bufB);
    cudaGetSymbolAddress((void**)&bufC, g_bufC);

    const int T = 256;

    // CSR build + node metadata
    zero_kernel<<<ceil_div(M, T), T>>>(M);
    count_kernel<<<ceil_div(E, T), T>>>(ei, E);
    scan_kernel<<<1, 1024>>>(M);
    fill_kernel<<<ceil_div(E, T), T>>>(ei, E);
    node_prep<<<ceil_div(M, T), T>>>(x, nf, M);

    int gblocks = ceil_div(M, 8);  // 8 warps per block

    // ---- Layer 1: Hs = dinv*x; gather(100) -> agg; GEMM K=100 -> 512 (+b1, relu)
    scale_x<<<ceil_div((long long)M * INDIM, T), T>>>(x, bufA, M);
    gather_kernel<<<gblocks, 256>>>(bufA, bufB, nullptr, M, INDIM, 0);
    {
        dim3 g(ceil_div(M, 128), ceil_div(D1, 64));
        gemm_kernel<<<g, 256>>>(bufB, W1, b1, bufC, M, INDIM, D1, 0);
    }

    // ---- Layer 2: GEMM 512->256 (epi dinv => Hs); gather(256) (+b2, relu)
    {
        dim3 g(ceil_div(M, 128), ceil_div(D2, 64));
        gemm_kernel<<<g, 256>>>(bufC, W2, nullptr, bufA, M, D1, D2, 1);
    }
    gather_kernel<<<gblocks, 256>>>(bufA, bufB, b2, M, D2, 1);

    // ---- Layer 3: GEMM 256->128 (epi dinv => Hs); gather(128) (+b3, relu, *dinv => Hs4)
    {
        dim3 g(ceil_div(M, 128), ceil_div(D3, 64));
        gemm_kernel<<<g, 256>>>(bufB, W3, nullptr, bufA, M, D2, D3, 1);
    }
    gather_kernel<<<gblocks, 256>>>(bufA, bufB, b3, M, D3, 2);

    // ---- Layer 4: gather(128) -> agg; GEMM 128->200 (+b4, relu)
    gather_kernel<<<gblocks, 256>>>(bufB, bufA, nullptr, M, D3, 0);
    {
        dim3 g(ceil_div(M, 128), ceil_div(D4, 64));
        gemm_kernel<<<g, 256>>>(bufA, W4, b4, bufC, M, D3, D4, 0);
    }

    // ---- grouped mean pooling
    group_reduce<<<ceil_div(M, 256), 128>>>(bufC, M);
    final_out<<<ceil_div(4 * D4, T), T>>>(out);
}